// round 7
// baseline (speedup 1.0000x reference)
#include <cuda_runtime.h>
#include <cuda_bf16.h>

#define NLAT 46
#define NLON 90
#define CH   256
#define SPX  (NLAT * NLON)   // 4140 spatial points

// Heavy rows: 0, 1, 44, 45 (pole rows + their full-pole-circle neighbors)
#define HEAVY_BLOCKS (4 * NLON)                 // 360: one CTA per heavy point
#define LIGHT_BEG    (2 * NLON)                 // pos 180  (row 2)
#define LIGHT_END    (44 * NLON)                // pos 3960 (end of row 43)
#define LIGHT_BLOCKS ((LIGHT_END - LIGHT_BEG + 7) / 8)   // 473

#define MAXNNZ 4096

// Scratch
__device__ float g_qc[CH * SPX];   // q channel-major [c][s]
__device__ float g_kc[CH * SPX];   // k channel-major [c][s]
__device__ float g_v [SPX * CH];   // v spatial-major [s][c]
__device__ float g_s [MAXNNZ * NLON];  // scores S[n][wo]
__device__ int   g_off[NLAT + 1];

// f32x2 packed FMA (Blackwell): d = a * b + d on two packed floats.
#define FMA_F32X2(d, a, b) \
    asm("fma.rn.f32x2 %0, %1, %2, %0;" : "+l"(d) : "l"(a), "l"(b))
#define DUP_F32X2(d, x) \
    asm("mov.b64 %0, {%1, %1};" : "=l"(d) : "r"(__float_as_uint(x)))

// ---------------------------------------------------------------------------
// Fused projection GEMM (q, k, v by blockIdx.z):
//   out[s][n] or out[n][s] = sum_c W[n][c] * X[c][s] + b[n]
// BM=64 x BN=64 x BK=16, 64 threads, 8x8 micro-tile via fma.rn.f32x2.
// q,k stored channel-major (for the score pass); v spatial-major (for output).
// Block (0,0,0) also computes segment offsets.
// ---------------------------------------------------------------------------
__global__ void __launch_bounds__(64) proj_kernel(
    const float* __restrict__ qo, const float* __restrict__ ki,
    const float* __restrict__ vi,
    const float* __restrict__ q_w, const float* __restrict__ k_w,
    const float* __restrict__ v_w,
    const float* __restrict__ q_b, const float* __restrict__ k_b,
    const float* __restrict__ v_b,
    const int* __restrict__ row_ids, int nnz)
{
    const int which = blockIdx.z;
    const float* X    = (which == 0) ? qo  : (which == 1) ? ki  : vi;
    const float* W    = (which == 0) ? q_w : (which == 1) ? k_w : v_w;
    const float* bias = (which == 0) ? q_b : (which == 1) ? k_b : v_b;
    float* out        = (which == 0) ? g_qc : (which == 1) ? g_kc : g_v;

    const int tid = threadIdx.x;

    if (which == 0 && blockIdx.x == 0 && blockIdx.y == 0 && tid <= NLAT) {
        int lo = 0, hi = nnz;
        while (lo < hi) {
            int mid = (lo + hi) >> 1;
            if (row_ids[mid] < tid) lo = mid + 1; else hi = mid;
        }
        g_off[tid] = lo;
    }

    __shared__ __align__(16) float Xs[16][64];
    __shared__ __align__(16) float Ws[16][68];

    const int s0 = blockIdx.x * 64;
    const int n0 = blockIdx.y * 64;

    const int tm = (tid >> 3) * 4;   // 0..28
    const int tn = (tid & 7) * 4;    // 0..28

    // Packed accumulators: acc2[i][j] = channels {tn+2j, tn+2j+1} (j<2)
    //                                or {tn+32+2(j-2), +1}        (j>=2), row s=tm+i / tm+32+i-4
    unsigned long long acc2[8][4] = {};

    for (int c0 = 0; c0 < CH; c0 += 16) {
        #pragma unroll
        for (int r = 0; r < 4; ++r) {
            int idx = r * 64 + tid;
            int kk = idx >> 4, sm4 = idx & 15;
            int s = s0 + sm4 * 4;
            float4 xv = make_float4(0.f, 0.f, 0.f, 0.f);
            if (s < SPX)
                xv = *(const float4*)&X[(c0 + kk) * SPX + s];
            *(float4*)&Xs[kk][sm4 * 4] = xv;
        }
        #pragma unroll
        for (int r = 0; r < 4; ++r) {
            int idx = r * 64 + tid;
            int kn = idx >> 2, kk4 = (idx & 3) * 4;
            float4 wv = *(const float4*)&W[(n0 + kn) * CH + c0 + kk4];
            Ws[kk4 + 0][kn] = wv.x;
            Ws[kk4 + 1][kn] = wv.y;
            Ws[kk4 + 2][kn] = wv.z;
            Ws[kk4 + 3][kn] = wv.w;
        }
        __syncthreads();

        #pragma unroll
        for (int kk = 0; kk < 16; ++kk) {
            float4 a0 = *(const float4*)&Xs[kk][tm];
            float4 a1 = *(const float4*)&Xs[kk][tm + 32];
            // w pairs straight out of shared (16B-aligned rows)
            unsigned long long w2[4];
            {
                const unsigned long long* wp0 =
                    (const unsigned long long*)&Ws[kk][tn];
                const unsigned long long* wp1 =
                    (const unsigned long long*)&Ws[kk][tn + 32];
                w2[0] = wp0[0]; w2[1] = wp0[1];
                w2[2] = wp1[0]; w2[3] = wp1[1];
            }
            unsigned long long av2[8];
            DUP_F32X2(av2[0], a0.x); DUP_F32X2(av2[1], a0.y);
            DUP_F32X2(av2[2], a0.z); DUP_F32X2(av2[3], a0.w);
            DUP_F32X2(av2[4], a1.x); DUP_F32X2(av2[5], a1.y);
            DUP_F32X2(av2[6], a1.z); DUP_F32X2(av2[7], a1.w);
            #pragma unroll
            for (int i = 0; i < 8; ++i)
                #pragma unroll
                for (int j = 0; j < 4; ++j)
                    FMA_F32X2(acc2[i][j], av2[i], w2[j]);
        }
        __syncthreads();
    }

    // Unpack
    float acc[8][8];
    #pragma unroll
    for (int i = 0; i < 8; ++i)
        #pragma unroll
        for (int j = 0; j < 4; ++j) {
            float2 f = *(float2*)&acc2[i][j];
            acc[i][2 * j]     = f.x;
            acc[i][2 * j + 1] = f.y;
        }

    float bv[8];
    #pragma unroll
    for (int j = 0; j < 4; ++j) {
        bv[j]     = __ldg(&bias[n0 + tn + j]);
        bv[j + 4] = __ldg(&bias[n0 + tn + 32 + j]);
    }

    if (which == 2) {
        // v: spatial-major [s][c]
        #pragma unroll
        for (int i = 0; i < 8; ++i) {
            int s = s0 + ((i < 4) ? (tm + i) : (tm + 32 + i - 4));
            if (s < SPX) {
                float4 o0, o1;
                o0.x = acc[i][0] + bv[0];  o0.y = acc[i][1] + bv[1];
                o0.z = acc[i][2] + bv[2];  o0.w = acc[i][3] + bv[3];
                o1.x = acc[i][4] + bv[4];  o1.y = acc[i][5] + bv[5];
                o1.z = acc[i][6] + bv[6];  o1.w = acc[i][7] + bv[7];
                *(float4*)&out[s * CH + n0 + tn]      = o0;
                *(float4*)&out[s * CH + n0 + tn + 32] = o1;
            }
        }
    } else {
        // q,k: channel-major [c][s], float4 along s (SPX % 4 == 0)
        #pragma unroll
        for (int j = 0; j < 8; ++j) {
            int c = n0 + ((j < 4) ? (tn + j) : (tn + 28 + j));
            float b = bv[j];
            float4 lo, hi;
            lo.x = acc[0][j] + b; lo.y = acc[1][j] + b;
            lo.z = acc[2][j] + b; lo.w = acc[3][j] + b;
            hi.x = acc[4][j] + b; hi.y = acc[5][j] + b;
            hi.z = acc[6][j] + b; hi.w = acc[7][j] + b;
            if (s0 + tm < SPX)      *(float4*)&out[c * SPX + s0 + tm]      = lo;
            if (s0 + tm + 32 < SPX) *(float4*)&out[c * SPX + s0 + tm + 32] = hi;
        }
    }
}

// ---------------------------------------------------------------------------
// Score pass: S[n][wo] = exp(q[t_n,wo] . k[h_n,(w_n+wo)%NLON]) * quad[h_n]
// One warp per (neighbor n, 32-wide wo block). Lanes span wo -> coalesced.
// Thread-local 256-FMA dot: no shuffles, no serial cross-lane chain.
// ---------------------------------------------------------------------------
__global__ void __launch_bounds__(256) score_kernel(
    const int*   __restrict__ row_ids,
    const int*   __restrict__ col_idx,
    const float* __restrict__ quad,
    int nnz)
{
    const int w    = (int)((blockIdx.x * 256 + threadIdx.x) >> 5);
    const int lane = threadIdx.x & 31;
    const int n    = w / 3;
    const int wb   = w - n * 3;
    if (n >= nnz) return;

    const int t   = __ldg(&row_ids[n]);
    const int ci  = __ldg(&col_idx[n]);
    const int hi  = ci / NLON;
    const int wi0 = ci - hi * NLON;

    const int wo  = wb * 32 + lane;
    const bool act = (wo < NLON);
    const int woc = act ? wo : 0;
    int wi = wi0 + woc;
    if (wi >= NLON) wi -= NLON;

    const float* qp = g_qc + t * NLON + woc;
    const float* kp = g_kc + hi * NLON + wi;

    float p0 = 0.f, p1 = 0.f, p2 = 0.f, p3 = 0.f;
    #pragma unroll 4
    for (int c = 0; c < CH; c += 4) {
        p0 += qp[0 * SPX] * kp[0 * SPX];
        p1 += qp[1 * SPX] * kp[1 * SPX];
        p2 += qp[2 * SPX] * kp[2 * SPX];
        p3 += qp[3 * SPX] * kp[3 * SPX];
        qp += 4 * SPX; kp += 4 * SPX;
    }
    float e = __expf((p0 + p1) + (p2 + p3)) * __ldg(&quad[hi]);
    if (act) g_s[n * NLON + wo] = e;
}

// ---------------------------------------------------------------------------
// Output pass: out[c][pos] = sum_n S[n][wo] * v[nbr][c] / sum_n S[n][wo]
// Heavy (rows 0,1,44,45): one CTA per point, 8 warps stride neighbors.
// Light (rows 2..43): warp per point, smem-transposed coalesced store.
// Loop body is load+FMA only — fully pipelined.
// ---------------------------------------------------------------------------
__device__ __forceinline__ void out_step(
    int n, int wo, int lane,
    const int* __restrict__ col_idx,
    float& d, float4& a0, float4& a1)
{
    int ci = __ldg(&col_idx[n]);
    int hi = ci / NLON;
    int wi = ci - hi * NLON + wo;
    if (wi >= NLON) wi -= NLON;
    int base = (hi * NLON + wi) * CH;

    float e = __ldg(&g_s[n * NLON + wo]);

    const float4* vv = (const float4*)(g_v + base);
    float4 v0 = vv[lane];
    float4 v1 = vv[lane + 32];

    d += e;
    a0.x += e * v0.x;  a0.y += e * v0.y;
    a0.z += e * v0.z;  a0.w += e * v0.w;
    a1.x += e * v1.x;  a1.y += e * v1.y;
    a1.z += e * v1.z;  a1.w += e * v1.w;
}

__global__ void __launch_bounds__(256) attn_out_kernel(
    const int* __restrict__ col_idx,
    float*     __restrict__ out)
{
    __shared__ float smem[2304];   // heavy: [8][256]+[8] | light: [256][9]

    const int warp = threadIdx.x >> 5;
    const int lane = threadIdx.x & 31;

    if (blockIdx.x < HEAVY_BLOCKS) {
        const int bi = blockIdx.x;
        int r = bi / NLON;                    // 0..3
        const int t  = (r < 2) ? r : (NLAT - 4 + r);   // 0,1,44,45
        const int wo = bi - r * NLON;
        const int pos = t * NLON + wo;

        float d = 0.0f;
        float4 a0 = make_float4(0.f, 0.f, 0.f, 0.f);
        float4 a1 = make_float4(0.f, 0.f, 0.f, 0.f);

        const int beg = g_off[t];
        const int end = g_off[t + 1];

        #pragma unroll 2
        for (int n = beg + warp; n < end; n += 8)
            out_step(n, wo, lane, col_idx, d, a0, a1);

        float* sb = smem + warp * 256;
        *(float4*)&sb[lane * 4]       = a0;
        *(float4*)&sb[128 + lane * 4] = a1;
        if (lane == 0) smem[2048 + warp] = d;
        __syncthreads();

        const int c = threadIdx.x;
        float s = 0.0f, dt = 0.0f;
        #pragma unroll
        for (int w = 0; w < 8; ++w) s  += smem[w * 256 + c];
        #pragma unroll
        for (int w = 0; w < 8; ++w) dt += smem[2048 + w];
        out[c * SPX + pos] = s / dt;
    } else {
        const int pos0 = LIGHT_BEG + (blockIdx.x - HEAVY_BLOCKS) * 8;
        const int gw   = pos0 + warp;

        if (gw < LIGHT_END) {
            const int t  = gw / NLON;
            const int wo = gw - t * NLON;

            float d = 0.0f;
            float4 a0 = make_float4(0.f, 0.f, 0.f, 0.f);
            float4 a1 = make_float4(0.f, 0.f, 0.f, 0.f);

            const int beg = g_off[t];
            const int end = g_off[t + 1];

            #pragma unroll 2
            for (int n = beg; n < end; ++n)
                out_step(n, wo, lane, col_idx, d, a0, a1);

            const float inv = 1.0f / d;
            const int c0 = lane * 4;
            smem[(c0 + 0) * 9 + warp] = a0.x * inv;
            smem[(c0 + 1) * 9 + warp] = a0.y * inv;
            smem[(c0 + 2) * 9 + warp] = a0.z * inv;
            smem[(c0 + 3) * 9 + warp] = a0.w * inv;
            smem[(c0 + 128) * 9 + warp] = a1.x * inv;
            smem[(c0 + 129) * 9 + warp] = a1.y * inv;
            smem[(c0 + 130) * 9 + warp] = a1.z * inv;
            smem[(c0 + 131) * 9 + warp] = a1.w * inv;
        }
        __syncthreads();

        const int p  = threadIdx.x & 7;
        const int cb = threadIdx.x >> 3;
        if (pos0 + p < LIGHT_END) {
            #pragma unroll
            for (int j = 0; j < 8; ++j) {
                int c = cb + j * 32;
                out[c * SPX + pos0 + p] = smem[c * 9 + p];
            }
        }
    }
}

// ---------------------------------------------------------------------------
extern "C" void kernel_launch(void* const* d_in, const int* in_sizes, int n_in,
                              void* d_out, int out_size)
{
    const float* qo   = (const float*)d_in[0];
    const float* ki   = (const float*)d_in[1];
    const float* vi   = (const float*)d_in[2];
    const float* q_w  = (const float*)d_in[3];
    const float* k_w  = (const float*)d_in[4];
    const float* v_w  = (const float*)d_in[5];
    const float* q_b  = (const float*)d_in[6];
    const float* k_b  = (const float*)d_in[7];
    const float* v_b  = (const float*)d_in[8];
    const float* quad = (const float*)d_in[9];
    const int* row_ids = (const int*)d_in[10];
    const int* col_idx = (const int*)d_in[11];
    const int nnz = in_sizes[10];

    float* out = (float*)d_out;

    dim3 gg((SPX + 63) / 64, CH / 64, 3);
    proj_kernel<<<gg, 64>>>(qo, ki, vi, q_w, k_w, v_w, q_b, k_b, v_b,
                            row_ids, nnz);

    int score_warps = 3 * nnz;
    score_kernel<<<(score_warps + 7) / 8, 256>>>(row_ids, col_idx, quad, nnz);

    attn_out_kernel<<<HEAVY_BLOCKS + LIGHT_BLOCKS, 256>>>(col_idx, out);
}